// round 6
// baseline (speedup 1.0000x reference)
#include <cuda_runtime.h>
#include <math.h>

#define BB 128
#define QQ 500
#define NCLS 80
#define TT 64
#define FULL 0xffffffffu
#define NBX 16          // q-blocks per image in cost kernel (32 q each)

// per-(image, q-block, column) partial min keys: (f2ord(cost)<<15) | (q<<6) | t
__device__ unsigned long long g_part[BB * NBX * TT];

__device__ __forceinline__ unsigned int f2ord(float f) {
    unsigned int u = __float_as_uint(f);
    return (u & 0x80000000u) ? ~u : (u | 0x80000000u);
}

// ================= Kernel A: cost matrix + partial column minima =================
#define KA_THREADS 256

__global__ __launch_bounds__(KA_THREADS)
void cost_kernel(const float* __restrict__ logits,   // [B,Q,C]
                 const float* __restrict__ pboxes,   // [B,Q,4]
                 const int*   __restrict__ tids,     // [B,T]
                 const float* __restrict__ tboxes,   // [B,T,4]
                 const float* __restrict__ imgsz,    // [B,4]
                 float*       __restrict__ out)      // [B,Q,T]
{
    __shared__ float4 s_tr[TT];
    __shared__ float4 s_tn[TT];
    __shared__ float  s_ta[TT];
    __shared__ int    s_cls[TT];
    __shared__ unsigned long long s_part[TT];

    const int b   = blockIdx.y;
    const int bx  = blockIdx.x;
    const int tid = threadIdx.x;

    const float inv0 = 1.0f / imgsz[b * 4 + 0];
    const float inv1 = 1.0f / imgsz[b * 4 + 1];
    const float inv2 = 1.0f / imgsz[b * 4 + 2];
    const float inv3 = 1.0f / imgsz[b * 4 + 3];

    if (tid < TT) {
        float4 tb = ((const float4*)tboxes)[b * TT + tid];
        s_tr[tid] = tb;
        s_tn[tid] = make_float4(tb.x * inv0, tb.y * inv1, tb.z * inv2, tb.w * inv3);
        s_ta[tid] = (tb.z - tb.x) * (tb.w - tb.y);
        s_cls[tid] = tids[b * TT + tid];
        s_part[tid] = ~0ull;
    }
    __syncthreads();

    const int t = tid & 63;
    const float4 tr = s_tr[t];
    const float4 tn = s_tn[t];
    const float  ta = s_ta[t];
    const int    cl = s_cls[t];

    const float* lg   = logits + (size_t)b * QQ * NCLS;
    float*       Cout = out    + (size_t)b * QQ * TT;

    unsigned long long mink = ~0ull;

    #pragma unroll
    for (int rep = 0; rep < 4; rep++) {
        // two independent q-chains per rep for transcendental ILP
        #pragma unroll
        for (int half = 0; half < 2; half++) {
            int q = bx * 32 + rep * 8 + (tid >> 6) + half * 4;
            if (q >= QQ) continue;

            float4 pb = ((const float4*)pboxes)[b * QQ + q];
            float bnx = pb.x * inv0, bny = pb.y * inv1;
            float bnz = pb.z * inv2, bnw = pb.w * inv3;
            float pa  = (pb.z - pb.x) * (pb.w - pb.y);

            float x = __ldg(lg + q * NCLS + cl);
            float p = 1.0f / (1.0f + expf(-x));
            float omp = 1.0f - p;
            float pos = 0.25f * omp * omp * (-logf(p + 1e-8f));
            float neg = 0.75f * p * p * (-log1pf(-p + 1e-8f));
            float ccost = pos - neg;

            float l1 = fabsf(bnx - tn.x) + fabsf(bny - tn.y)
                     + fabsf(bnz - tn.z) + fabsf(bnw - tn.w);

            float iwd = fmaxf(fminf(pb.z, tr.z) - fmaxf(pb.x, tr.x), 0.0f);
            float ihd = fmaxf(fminf(pb.w, tr.w) - fmaxf(pb.y, tr.y), 0.0f);
            float inter = iwd * ihd;
            float uni = pa + ta - inter;
            float iou = inter / uni;
            float ewd = fmaxf(fmaxf(pb.z, tr.z) - fminf(pb.x, tr.x), 0.0f);
            float ehd = fmaxf(fmaxf(pb.w, tr.w) - fminf(pb.y, tr.y), 0.0f);
            float enc = ewd * ehd;
            float giou = iou - (enc - uni) / enc;

            float cost = 5.0f * l1 + 2.0f * ccost - 2.0f * giou;
            Cout[q * TT + t] = cost;

            unsigned long long key =
                ((unsigned long long)f2ord(cost) << 15) | (unsigned)((q << 6) | t);
            if (key < mink) mink = key;
        }
    }

    atomicMin(&s_part[t], mink);
    __syncthreads();
    if (tid < TT)
        g_part[(b * NBX + bx) * TT + tid] = s_part[tid];
}

// ================= Kernel B: greedy assignment (no C reload) =================
#define KB_THREADS 64

__global__ __launch_bounds__(KB_THREADS, 1)
void assign_kernel(const float* __restrict__ C,    // [B,Q,T]
                   float*       __restrict__ out)
{
    __shared__ unsigned s_val[TT];
    __shared__ unsigned s_rav[TT];
    __shared__ unsigned s_dead[16];      // 500-bit dead-row bitmap

    const int b = blockIdx.x, tid = threadIdx.x;
    const int lane = tid & 31;

    // init: reduce the 16 per-block partials for this column
    {
        const unsigned long long* pp = g_part + b * NBX * TT + tid;
        unsigned long long k = ~0ull;
        #pragma unroll
        for (int s = 0; s < NBX; s++) {
            unsigned long long v = __ldg(pp + s * TT);
            if (v < k) k = v;
        }
        s_val[tid] = (unsigned)(k >> 15);
        s_rav[tid] = (unsigned)(k & 0x7FFFull);
        if (tid < 16) s_dead[tid] = 0u;
    }
    __syncthreads();

    if (tid >= 32) return;   // greedy: warp 0 only

    unsigned v0 = s_val[lane],      r0 = s_rav[lane];        // col = lane
    unsigned v1 = s_val[lane + 32], r1 = s_rav[lane + 32];   // col = lane+32
    const unsigned DEAD = 0xFFFFFFFFu;

    const float* Cg = C + (size_t)b * QQ * TT;
    float* rows_out = out + (size_t)BB * QQ * TT + (size_t)b * TT;
    float* cols_out = rows_out + (size_t)BB * TT;

    #pragma unroll 1
    for (int s = 0; s < TT; s++) {
        unsigned m = __reduce_min_sync(FULL, v0 < v1 ? v0 : v1);
        unsigned cand = 0xFFFFFFFFu;
        if (v0 == m) cand = r0;
        if (v1 == m && r1 < cand) cand = r1;
        unsigned r = __reduce_min_sync(FULL, cand);   // exact (value, ravel) tie-break

        int i = (int)(r >> 6);
        int j = (int)(r & 63u);
        if (lane == 0) {
            rows_out[s] = (float)i;
            cols_out[s] = (float)j;
            s_dead[i >> 5] |= 1u << (i & 31);         // single-writer, fenced below
        }
        if (s == TT - 1) break;

        // kill column j
        if (lane == (j & 31)) { if (j < 32) v0 = DEAD; else v1 = DEAD; }

        // columns whose cached argmin row was just consumed must rescan (rare)
        bool n0 = (v0 != DEAD) && ((int)(r0 >> 6) == i);
        bool n1 = (v1 != DEAD) && ((int)(r1 >> 6) == i);
        unsigned bal0 = __ballot_sync(FULL, n0);
        unsigned bal1 = __ballot_sync(FULL, n1);
        if (bal0 | bal1) {
            __syncwarp();   // make dead-bitmap updates visible
            unsigned bal = bal0 | bal1;
            while (bal0 | bal1) {
                int c;
                if (bal0) { c = __ffs(bal0) - 1; bal0 &= bal0 - 1; }
                else      { c = (__ffs(bal1) - 1) + 32; bal1 &= bal1 - 1; }

                // warp-cooperative gmem column scan with dead-row masking
                unsigned best = 0xFFFFFFFFu, bq = 0;
                #pragma unroll
                for (int it = 0; it < 16; it++) {
                    int q = lane + it * 32;
                    if (q < QQ) {
                        unsigned dead = (s_dead[it] >> lane) & 1u;
                        float f = __ldg(Cg + q * TT + c);
                        unsigned u = dead ? 0xFFFFFFFFu : f2ord(f);
                        if (u < best) { best = u; bq = (unsigned)q; }
                    }
                }
                unsigned mv = __reduce_min_sync(FULL, best);
                unsigned cr = (best == mv) ? ((bq << 6) | (unsigned)c) : 0xFFFFFFFFu;
                unsigned mr = __reduce_min_sync(FULL, cr);
                if (c < 32) { if (lane == c)      { v0 = mv; r0 = mr; } }
                else        { if (lane == c - 32) { v1 = mv; r1 = mr; } }
            }
            (void)bal;
        }
    }
}

extern "C" void kernel_launch(void* const* d_in, const int* in_sizes, int n_in,
                              void* d_out, int out_size) {
    const float* logits = (const float*)d_in[0];   // [128,500,80]
    const float* pboxes = (const float*)d_in[1];   // [128,500,4]
    const int*   tids   = (const int*)  d_in[2];   // [128,64]
    const float* tboxes = (const float*)d_in[3];   // [128,64,4]
    const float* imgsz  = (const float*)d_in[4];   // [128,4]
    float* out = (float*)d_out;

    dim3 gA(NBX, BB);
    cost_kernel<<<gA, KA_THREADS>>>(logits, pboxes, tids, tboxes, imgsz, out);
    assign_kernel<<<BB, KB_THREADS>>>(out, out);
}